// round 4
// baseline (speedup 1.0000x reference)
#include <cuda_runtime.h>
#include <cuda_bf16.h>
#include <cstdint>

#define BB 32
#define TT 2048
#define II 256
#define HH 512
#define GG 2048   // 4*H

#define NCTA_R 64
#define NTH  256

// Scratch (device globals — no runtime allocation allowed)
__device__ float g_xg[134217728];                 // [T][B][4H] (512 MB)
__device__ __nv_bfloat16 g_hhi[2][BB * HH];       // ping-pong hidden (hi)
__device__ __nv_bfloat16 g_hlo[2][BB * HH];       // ping-pong hidden (lo)
__device__ int g_bar;                             // monotonic barrier counter

// ---------------------------------------------------------------------------
// Kernel A: xg[t*B+b][g] = sum_i x[b][t][i]*W_ih[g][i] + b_ih[g] + b_hh[g]
// (unchanged from R2)
// ---------------------------------------------------------------------------
__global__ void __launch_bounds__(256) xg_gemm_kernel(
    const float* __restrict__ x,
    const float* __restrict__ Wih,
    const float* __restrict__ bih,
    const float* __restrict__ bhh)
{
    __shared__ float a_sm[16][64];
    __shared__ float b_sm[16][64];

    const int tid = threadIdx.x;
    if (blockIdx.x == 0 && blockIdx.y == 0 && tid == 0) g_bar = 0;

    const int row0 = blockIdx.y * 64;
    const int col0 = blockIdx.x * 64;
    const int tx = tid & 15;
    const int ty = tid >> 4;

    const int lrow = tid & 63;
    const int kq   = tid >> 6;

    const int r = row0 + lrow;
    const int b = r & (BB - 1);
    const int t = r >> 5;
    const float* xrow = x + ((size_t)b * TT + t) * II;
    const float* wrow = Wih + (size_t)(col0 + lrow) * II;

    float acc[4][4] = {};

    for (int k0 = 0; k0 < II; k0 += 16) {
        float4 av = *(const float4*)(xrow + k0 + 4 * kq);
        float4 bv = *(const float4*)(wrow + k0 + 4 * kq);
        __syncthreads();
        a_sm[4 * kq + 0][lrow] = av.x;
        a_sm[4 * kq + 1][lrow] = av.y;
        a_sm[4 * kq + 2][lrow] = av.z;
        a_sm[4 * kq + 3][lrow] = av.w;
        b_sm[4 * kq + 0][lrow] = bv.x;
        b_sm[4 * kq + 1][lrow] = bv.y;
        b_sm[4 * kq + 2][lrow] = bv.z;
        b_sm[4 * kq + 3][lrow] = bv.w;
        __syncthreads();
#pragma unroll
        for (int kk = 0; kk < 16; kk++) {
            float4 a4 = *(const float4*)&a_sm[kk][ty * 4];
            float4 b4 = *(const float4*)&b_sm[kk][tx * 4];
            float aa[4] = {a4.x, a4.y, a4.z, a4.w};
            float bb[4] = {b4.x, b4.y, b4.z, b4.w};
#pragma unroll
            for (int i = 0; i < 4; i++)
#pragma unroll
                for (int j = 0; j < 4; j++)
                    acc[i][j] = fmaf(aa[i], bb[j], acc[i][j]);
        }
    }

    const int g0 = col0 + tx * 4;
    float4 bi = *(const float4*)(bih + g0);
    float4 bh = *(const float4*)(bhh + g0);
    float bias[4] = {bi.x + bh.x, bi.y + bh.y, bi.z + bh.z, bi.w + bh.w};
#pragma unroll
    for (int i = 0; i < 4; i++) {
        int row = row0 + ty * 4 + i;
        float4 o;
        o.x = acc[i][0] + bias[0];
        o.y = acc[i][1] + bias[1];
        o.z = acc[i][2] + bias[2];
        o.w = acc[i][3] + bias[3];
        *(float4*)(g_xg + (size_t)row * GG + g0) = o;
    }
}

// ---------------------------------------------------------------------------
// helpers
// ---------------------------------------------------------------------------
__device__ __forceinline__ void split2(float x, float y, uint32_t& hi, uint32_t& lo) {
    __nv_bfloat162 h = __floats2bfloat162_rn(x, y);
    float rx = x - __bfloat162float(h.x);
    float ry = y - __bfloat162float(h.y);
    __nv_bfloat162 l = __floats2bfloat162_rn(rx, ry);
    hi = *(uint32_t*)&h;
    lo = *(uint32_t*)&l;
}

// D = A(16x16 row) * B(16x8 col) + D, bf16 inputs, f32 accum
__device__ __forceinline__ void mma_bf16(float* c,
                                         uint32_t a0, uint32_t a1, uint32_t a2, uint32_t a3,
                                         uint32_t b0, uint32_t b1) {
    asm volatile(
        "mma.sync.aligned.m16n8k16.row.col.f32.bf16.bf16.f32 "
        "{%0,%1,%2,%3}, {%4,%5,%6,%7}, {%8,%9}, {%0,%1,%2,%3};"
        : "+f"(c[0]), "+f"(c[1]), "+f"(c[2]), "+f"(c[3])
        : "r"(a0), "r"(a1), "r"(a2), "r"(a3), "r"(b0), "r"(b1));
}

__device__ __forceinline__ float sigf(float v) {
    return 1.0f / (1.0f + __expf(-v));
}

// smem layout (bytes). h rows padded: 520 bf16 = 1040 B per batch row.
#define HROWB 1040
#define SM_HHI 0                 // 32*1040 = 33280
#define SM_HLO 33280             // 33280
#define SM_RED 66560             // 8*32*40*4 = 40960  (f32 [8][32][40])
#define SM_GT  107520            // 32*36*4 = 4608     (f32 [row=32][36])
#define SM_XG  112128            // 32*40*4 = 5120     (f32 [b=32][40]: g*8+col)
#define SM_TOT 117760

// ---------------------------------------------------------------------------
// Kernel B: persistent mma.sync recurrence. 64 CTAs x 256 threads.
// CTA owns 8 H-cols -> 32 gate rows (r = gate*8 + colLocal).
// D[32,32] = A[32,512] * h[32,512]^T via 3 bf16 passes, W frags in registers.
// 8 warps split K (64 each), m16n8k16, split-K reduced in smem.
// ---------------------------------------------------------------------------
__global__ void __launch_bounds__(NTH, 1) lstm_rec_mma(
    const float* __restrict__ Whh,
    const float* __restrict__ h0,
    const float* __restrict__ c0,
    float* __restrict__ out,
    long long out_size)
{
    extern __shared__ char smem[];
    float* redp = (float*)(smem + SM_RED);
    float* gtp  = (float*)(smem + SM_GT);
    float* xgp  = (float*)(smem + SM_XG);

    const int tid = threadIdx.x;
    const int cta = blockIdx.x;
    const int col0 = cta * 8;

    const int w  = tid >> 5;   // warp: K slice [64w, 64w+64)
    const int l  = tid & 31;
    const int g4 = l >> 2;     // fragment group row / batch lane
    const int t4 = l & 3;

    // --- Preload W fragments (hi/lo) into registers: [mt][kt][a0..a3] ---
    uint32_t whi[2][4][4], wlo[2][4][4];
#pragma unroll
    for (int mt = 0; mt < 2; mt++) {
#pragma unroll
        for (int kt = 0; kt < 4; kt++) {
            const int k = 64 * w + 16 * kt + 2 * t4;
            const int r0 = mt * 16 + g4;
            const int r1 = r0 + 8;
            const int grow0 = (r0 >> 3) * HH + col0 + (r0 & 7);
            const int grow1 = (r1 >> 3) * HH + col0 + (r1 & 7);
            float2 v;
            v = *(const float2*)(Whh + (size_t)grow0 * HH + k);
            split2(v.x, v.y, whi[mt][kt][0], wlo[mt][kt][0]);
            v = *(const float2*)(Whh + (size_t)grow1 * HH + k);
            split2(v.x, v.y, whi[mt][kt][1], wlo[mt][kt][1]);
            v = *(const float2*)(Whh + (size_t)grow0 * HH + k + 8);
            split2(v.x, v.y, whi[mt][kt][2], wlo[mt][kt][2]);
            v = *(const float2*)(Whh + (size_t)grow1 * HH + k + 8);
            split2(v.x, v.y, whi[mt][kt][3], wlo[mt][kt][3]);
        }
    }

    // B-fragment smem base for this lane (byte offset into hhi/hlo region)
    const uint32_t bfrag_off = (uint32_t)(g4 * HROWB + (64 * w + 2 * t4) * 2);

    // activation identity: colL = tid&7, b = tid>>3
    const int colL = tid & 7;
    const int b_act = tid >> 3;
    const int colG = col0 + colL;
    float c_reg = c0[b_act * HH + colG];

    const long long BTH = (long long)BB * TT * HH;
    const bool tails = (out_size >= BTH + 2LL * BB * HH);
    volatile int* vbar = &g_bar;

    for (int t = 0; t < TT; t++) {
        // ---- Phase 1: fill h hi/lo smem (padded rows) + xg smem ----
        if (t == 0) {
#pragma unroll 1
            for (int j = 0; j < 8; j++) {
                int chunk = tid + NTH * j;          // 0..2047, 8 bf16 each
                int row = chunk >> 6;
                int k0 = (chunk & 63) * 8;
                const float4* s = (const float4*)(h0 + row * HH + k0);
                float4 a = s[0], b = s[1];
                uint4 hv, lv;
                split2(a.x, a.y, hv.x, lv.x);
                split2(a.z, a.w, hv.y, lv.y);
                split2(b.x, b.y, hv.z, lv.z);
                split2(b.z, b.w, hv.w, lv.w);
                uint32_t off = row * HROWB + k0 * 2;
                *(uint4*)(smem + SM_HHI + off) = hv;
                *(uint4*)(smem + SM_HLO + off) = lv;
            }
        } else {
            const uint4* shi = (const uint4*)g_hhi[t & 1];
            const uint4* slo = (const uint4*)g_hlo[t & 1];
#pragma unroll 1
            for (int j = 0; j < 8; j++) {
                int chunk = tid + NTH * j;
                int row = chunk >> 6;
                int c16 = chunk & 63;
                uint32_t off = row * HROWB + c16 * 16;
                *(uint4*)(smem + SM_HHI + off) = __ldcg(shi + chunk);
                *(uint4*)(smem + SM_HLO + off) = __ldcg(slo + chunk);
            }
        }
        // xg slice: [b][gate*8 + col] with b-stride 40 words
        {
            int b = tid >> 3;
            int gq = (tid >> 1) & 3;
            int hf = tid & 1;
            float4 v = *(const float4*)(g_xg + ((size_t)t * BB + b) * GG + gq * HH + col0 + 4 * hf);
            *(float4*)(xgp + b * 40 + gq * 8 + 4 * hf) = v;
        }
        __syncthreads();

        // ---- Phase 2: GEMM (per-warp K slice), 3 passes fused ----
        float acc[2][4][4] = {};
#pragma unroll
        for (int nt = 0; nt < 4; nt++) {
#pragma unroll
            for (int kt = 0; kt < 4; kt++) {
                uint32_t off = bfrag_off + nt * (8 * HROWB) + kt * 32;
                uint32_t bh0 = *(const uint32_t*)(smem + SM_HHI + off);
                uint32_t bh1 = *(const uint32_t*)(smem + SM_HHI + off + 16);
                uint32_t bl0 = *(const uint32_t*)(smem + SM_HLO + off);
                uint32_t bl1 = *(const uint32_t*)(smem + SM_HLO + off + 16);
#pragma unroll
                for (int mt = 0; mt < 2; mt++) {
                    mma_bf16(acc[mt][nt], whi[mt][kt][0], whi[mt][kt][1], whi[mt][kt][2], whi[mt][kt][3], bh0, bh1);
                    mma_bf16(acc[mt][nt], whi[mt][kt][0], whi[mt][kt][1], whi[mt][kt][2], whi[mt][kt][3], bl0, bl1);
                    mma_bf16(acc[mt][nt], wlo[mt][kt][0], wlo[mt][kt][1], wlo[mt][kt][2], wlo[mt][kt][3], bh0, bh1);
                }
            }
        }

        // store split-K partials: red[w][row][b] (row stride 40)
        {
            float* rw = redp + w * 1280;
#pragma unroll
            for (int mt = 0; mt < 2; mt++) {
#pragma unroll
                for (int nt = 0; nt < 4; nt++) {
                    int row0 = mt * 16 + g4;
                    int cc = 8 * nt + 2 * t4;
                    *(float2*)&rw[row0 * 40 + cc] = make_float2(acc[mt][nt][0], acc[mt][nt][1]);
                    *(float2*)&rw[(row0 + 8) * 40 + cc] = make_float2(acc[mt][nt][2], acc[mt][nt][3]);
                }
            }
        }
        __syncthreads();

        // ---- Phase 3: split-K reduction -> gates smem ----
        {
            int row = tid >> 3;
            int bq = tid & 7;
            float4 s = make_float4(0.f, 0.f, 0.f, 0.f);
#pragma unroll
            for (int w2 = 0; w2 < 8; w2++) {
                float4 p = *(float4*)&redp[w2 * 1280 + row * 40 + 4 * bq];
                s.x += p.x; s.y += p.y; s.z += p.z; s.w += p.w;
            }
            *(float4*)&gtp[row * 36 + 4 * bq] = s;
        }
        __syncthreads();

        // ---- Phase 4: activations + state update ----
        {
            float gi = gtp[(0 * 8 + colL) * 36 + b_act] + xgp[b_act * 40 + 0 * 8 + colL];
            float gf = gtp[(1 * 8 + colL) * 36 + b_act] + xgp[b_act * 40 + 1 * 8 + colL];
            float gg = gtp[(2 * 8 + colL) * 36 + b_act] + xgp[b_act * 40 + 2 * 8 + colL];
            float go = gtp[(3 * 8 + colL) * 36 + b_act] + xgp[b_act * 40 + 3 * 8 + colL];
            float ig = sigf(gi);
            float fg = sigf(gf);
            float gt = tanhf(gg);
            float og = sigf(go);
            float cn = fmaf(fg, c_reg, ig * gt);
            float hn = og * tanhf(cn);
            c_reg = cn;

            out[((size_t)b_act * TT + t) * HH + colG] = hn;

            __nv_bfloat16 hh = __float2bfloat16(hn);
            __nv_bfloat16 hl = __float2bfloat16(hn - __bfloat162float(hh));
            int hidx = b_act * HH + colG;
            g_hhi[(t + 1) & 1][hidx] = hh;
            g_hlo[(t + 1) & 1][hidx] = hl;

            if (t == TT - 1 && tails) {
                out[BTH + (long long)b_act * HH + colG] = hn;
                out[BTH + (long long)BB * HH + (long long)b_act * HH + colG] = cn;
            }
        }
        __threadfence();
        __syncthreads();
        // ---- grid barrier (monotonic counter reset by kernel A) ----
        if (tid == 0) {
            atomicAdd(&g_bar, 1);
            int target = NCTA_R * (t + 1);
            while (*vbar < target) __nanosleep(32);
            __threadfence();
        }
        __syncthreads();
    }
}

// ---------------------------------------------------------------------------
// Inputs (metadata order): x, h0, c0, W_ih, W_hh, b_ih, b_hh
// Output: concat(result[B,T,H], h_f[1,B,H], c_f[1,B,H])
// ---------------------------------------------------------------------------
extern "C" void kernel_launch(void* const* d_in, const int* in_sizes, int n_in,
                              void* d_out, int out_size) {
    const float* x   = (const float*)d_in[0];
    const float* h0  = (const float*)d_in[1];
    const float* c0  = (const float*)d_in[2];
    const float* Wih = (const float*)d_in[3];
    const float* Whh = (const float*)d_in[4];
    const float* bih = (const float*)d_in[5];
    const float* bhh = (const float*)d_in[6];
    float* out = (float*)d_out;

    cudaFuncSetAttribute(lstm_rec_mma, cudaFuncAttributeMaxDynamicSharedMemorySize, SM_TOT);

    dim3 gridA(GG / 64, (TT * BB) / 64);
    xg_gemm_kernel<<<gridA, 256>>>(x, Wih, bih, bhh);
    lstm_rec_mma<<<NCTA_R, NTH, SM_TOT>>>(Whh, h0, c0, out, (long long)out_size);
}

// round 6
// speedup vs baseline: 1.5962x; 1.5962x over previous
#include <cuda_runtime.h>
#include <cuda_bf16.h>
#include <cstdint>

#define BB 32
#define TT 2048
#define II 256
#define HH 512
#define GG 2048   // 4*H

#define NCTA_R 64
#define NTH  256

// Scratch (device globals — no runtime allocation allowed; zero-initialized)
__device__ __nv_bfloat16 g_xbhi[BB * TT * II];    // x hi plane [b][t][i] (32 MB)
__device__ __nv_bfloat16 g_xblo[BB * TT * II];    // x lo plane (32 MB)
__device__ __nv_bfloat16 g_hhi[2][BB * HH];       // ping-pong hidden (hi)
__device__ __nv_bfloat16 g_hlo[2][BB * HH];       // ping-pong hidden (lo)
__device__ int g_flag[NCTA_R * 32];               // per-CTA monotonic flags (128B apart)

// ---------------------------------------------------------------------------
// helpers
// ---------------------------------------------------------------------------
__device__ __forceinline__ void split2(float x, float y, uint32_t& hi, uint32_t& lo) {
    __nv_bfloat162 h = __floats2bfloat162_rn(x, y);
    float rx = x - __bfloat162float(h.x);
    float ry = y - __bfloat162float(h.y);
    __nv_bfloat162 l = __floats2bfloat162_rn(rx, ry);
    hi = *(uint32_t*)&h;
    lo = *(uint32_t*)&l;
}

__device__ __forceinline__ void mma_bf16(float* c,
                                         uint32_t a0, uint32_t a1, uint32_t a2, uint32_t a3,
                                         uint32_t b0, uint32_t b1) {
    asm volatile(
        "mma.sync.aligned.m16n8k16.row.col.f32.bf16.bf16.f32 "
        "{%0,%1,%2,%3}, {%4,%5,%6,%7}, {%8,%9}, {%0,%1,%2,%3};"
        : "+f"(c[0]), "+f"(c[1]), "+f"(c[2]), "+f"(c[3])
        : "r"(a0), "r"(a1), "r"(a2), "r"(a3), "r"(b0), "r"(b1));
}

__device__ __forceinline__ float sigf(float v) {
    return 1.0f / (1.0f + __expf(-v));
}

__device__ __forceinline__ uint32_t smem_u32(const void* p) {
    uint32_t a;
    asm("{ .reg .u64 t; cvta.to.shared.u64 t, %1; cvt.u32.u64 %0, t; }" : "=r"(a) : "l"(p));
    return a;
}

__device__ __forceinline__ void cp_async8(uint32_t dst, const void* src) {
    asm volatile("cp.async.ca.shared.global [%0], [%1], 8;" :: "r"(dst), "l"(src) : "memory");
}

// ---------------------------------------------------------------------------
// Kernel 0: convert x to bf16 hi/lo planes (layout preserved [b][t][i])
// ---------------------------------------------------------------------------
__global__ void __launch_bounds__(256) xconv_kernel(const float* __restrict__ x) {
    const float2* src = (const float2*)x;
    uint32_t* dhi = (uint32_t*)g_xbhi;
    uint32_t* dlo = (uint32_t*)g_xblo;
    size_t n2 = (size_t)BB * TT * II / 2;
    for (size_t i = blockIdx.x * 256 + threadIdx.x; i < n2; i += (size_t)gridDim.x * 256) {
        float2 v = src[i];
        uint32_t hi, lo;
        split2(v.x, v.y, hi, lo);
        dhi[i] = hi;
        dlo[i] = lo;
    }
}

// smem layout (bytes)
// per-warp h region: 32 rows x 144B per plane; hi then lo (9216 B per warp)
#define HPITCH 144
#define SM_H   0                     // 8 * 9216 = 73728
#define SM_X   73728                 // 2 bufs x (hi 16896 + lo 16896) = 67584
#define XPITCH 528
#define XPLANE 16896                 // 32 * 528
#define XBUF   33792                 // hi+lo
#define SM_RED 141312                // 8*32*40*4 = 40960
#define SM_TOT 182272

// ---------------------------------------------------------------------------
// Fused persistent LSTM. 64 CTAs x 256 threads (8 warps).
// CTA owns 8 H-cols -> 32 gate rows (r = gate*8 + colL).
// gates = W_hh*h (K=512, 8-way K-split) + W_ih*x[t] (K=256) + bias,
// all via m16n8k16 bf16 3-pass (hi*hi + hi*lo + lo*hi), W frags in registers.
// Cross-CTA sync: 64 per-CTA monotonic flags; warp w polls its 8 producers.
// Safety: jointly the 8 warps confirm ALL 64 CTAs >= t+1 before publish, so
// the 2-deep ping-pong has no RAW/WAR hazard.
// ---------------------------------------------------------------------------
__global__ void __launch_bounds__(NTH, 1) lstm_fused(
    const float* __restrict__ h0,
    const float* __restrict__ c0,
    const float* __restrict__ Wih,
    const float* __restrict__ Whh,
    const float* __restrict__ bih,
    const float* __restrict__ bhh,
    float* __restrict__ out,
    long long out_size)
{
    extern __shared__ char smem[];
    float* redp = (float*)(smem + SM_RED);

    const int tid = threadIdx.x;
    const int cta = blockIdx.x;
    const int col0 = cta * 8;

    const int w  = tid >> 5;   // warp: h K-slice [64w, 64w+64), x K-slice [32w, 32w+32)
    const int l  = tid & 31;
    const int g4 = l >> 2;
    const int t4 = l & 3;

    // --- W_hh fragments (hi/lo) in registers ---
    uint32_t whi[2][4][4], wlo[2][4][4];
#pragma unroll
    for (int mt = 0; mt < 2; mt++)
#pragma unroll
        for (int kt = 0; kt < 4; kt++) {
            const int k = 64 * w + 16 * kt + 2 * t4;
            const int r0 = mt * 16 + g4;
            const int r1 = r0 + 8;
            const int grow0 = (r0 >> 3) * HH + col0 + (r0 & 7);
            const int grow1 = (r1 >> 3) * HH + col0 + (r1 & 7);
            float2 v;
            v = *(const float2*)(Whh + (size_t)grow0 * HH + k);
            split2(v.x, v.y, whi[mt][kt][0], wlo[mt][kt][0]);
            v = *(const float2*)(Whh + (size_t)grow1 * HH + k);
            split2(v.x, v.y, whi[mt][kt][1], wlo[mt][kt][1]);
            v = *(const float2*)(Whh + (size_t)grow0 * HH + k + 8);
            split2(v.x, v.y, whi[mt][kt][2], wlo[mt][kt][2]);
            v = *(const float2*)(Whh + (size_t)grow1 * HH + k + 8);
            split2(v.x, v.y, whi[mt][kt][3], wlo[mt][kt][3]);
        }

    // --- W_ih fragments (hi/lo) in registers ---
    uint32_t xwhi[2][2][4], xwlo[2][2][4];
#pragma unroll
    for (int mt = 0; mt < 2; mt++)
#pragma unroll
        for (int kt = 0; kt < 2; kt++) {
            const int k = 32 * w + 16 * kt + 2 * t4;
            const int r0 = mt * 16 + g4;
            const int r1 = r0 + 8;
            const int grow0 = (r0 >> 3) * HH + col0 + (r0 & 7);
            const int grow1 = (r1 >> 3) * HH + col0 + (r1 & 7);
            float2 v;
            v = *(const float2*)(Wih + (size_t)grow0 * II + k);
            split2(v.x, v.y, xwhi[mt][kt][0], xwlo[mt][kt][0]);
            v = *(const float2*)(Wih + (size_t)grow1 * II + k);
            split2(v.x, v.y, xwhi[mt][kt][1], xwlo[mt][kt][1]);
            v = *(const float2*)(Wih + (size_t)grow0 * II + k + 8);
            split2(v.x, v.y, xwhi[mt][kt][2], xwlo[mt][kt][2]);
            v = *(const float2*)(Wih + (size_t)grow1 * II + k + 8);
            split2(v.x, v.y, xwhi[mt][kt][3], xwlo[mt][kt][3]);
        }

    // --- activation identity + per-thread state ---
    const int colL = tid & 7;
    const int b_act = tid >> 3;
    const int colG = col0 + colL;
    float c_reg = c0[b_act * HH + colG];
    float bias_r[4];
#pragma unroll
    for (int g = 0; g < 4; g++)
        bias_r[g] = bih[g * HH + colG] + bhh[g * HH + colG];

    // --- flag base (monotonic across graph replays) ---
    const int F = *(volatile int*)&g_flag[cta * 32];

    // --- stage h0 slice (producer identity) into buffer 0 ---
    {
        float hv = h0[b_act * HH + colG];
        __nv_bfloat16 hh = __float2bfloat16(hv);
        g_hhi[0][b_act * HH + colG] = hh;
        g_hlo[0][b_act * HH + colG] = __float2bfloat16(hv - __bfloat162float(hh));
    }
    // --- stage x[0] into x buffer 0 via cp.async ---
    {
        char* xb = smem + SM_X;
#pragma unroll
        for (int j = 0; j < 8; j++) {
            int q = tid + NTH * j;
            int row = q >> 6;
            int c8 = q & 63;
            size_t src = ((size_t)row * TT + 0) * II + c8 * 4;
            cp_async8(smem_u32(xb + row * XPITCH + c8 * 8), g_xbhi + src);
            cp_async8(smem_u32(xb + XPLANE + row * XPITCH + c8 * 8), g_xblo + src);
        }
        asm volatile("cp.async.commit_group;" ::: "memory");
        asm volatile("cp.async.wait_all;" ::: "memory");
    }
    __threadfence();
    __syncthreads();
    if (tid == 0) *(volatile int*)&g_flag[cta * 32] = F + 1;

    const long long BTH = (long long)BB * TT * HH;
    const bool tails = (out_size >= BTH + 2LL * BB * HH);

    char* myh = smem + SM_H + w * 9216;
    const int pidx = (8 * w + (l & 7)) * 32;   // producer flag index for this lane

    for (int t = 0; t < TT; t++) {
        // ---- poll producer flags for my h K-slice ----
        {
            const int need = F + t + 1;
            while (__any_sync(0xffffffffu, *(volatile int*)&g_flag[pidx] < need))
                __nanosleep(20);
        }
        __threadfence();   // acquire: order flag read before data reads

        // ---- load h slice (hi/lo) -> warp-private smem ----
        {
            const __nv_bfloat16* shi = g_hhi[t & 1];
            const __nv_bfloat16* slo = g_hlo[t & 1];
#pragma unroll
            for (int j = 0; j < 8; j++) {
                int q = l + 32 * j;
                int row = q >> 3;
                int c8 = q & 7;
                *(uint4*)(myh + row * HPITCH + c8 * 16) =
                    __ldcg((const uint4*)(shi + row * HH + 64 * w + c8 * 8));
                *(uint4*)(myh + 4608 + row * HPITCH + c8 * 16) =
                    __ldcg((const uint4*)(slo + row * HH + 64 * w + c8 * 8));
            }
        }
        __syncwarp();

        // ---- MMA: h part (96) + x part (48) ----
        float acc[2][4][4] = {};
        {
            const uint32_t bo = (uint32_t)(g4 * HPITCH + (2 * t4) * 2);
#pragma unroll
            for (int nt = 0; nt < 4; nt++)
#pragma unroll
                for (int kt = 0; kt < 4; kt++) {
                    uint32_t off = bo + nt * (8 * HPITCH) + kt * 32;
                    uint32_t bh0 = *(const uint32_t*)(myh + off);
                    uint32_t bh1 = *(const uint32_t*)(myh + off + 16);
                    uint32_t bl0 = *(const uint32_t*)(myh + 4608 + off);
                    uint32_t bl1 = *(const uint32_t*)(myh + 4608 + off + 16);
#pragma unroll
                    for (int mt = 0; mt < 2; mt++) {
                        mma_bf16(acc[mt][nt], whi[mt][kt][0], whi[mt][kt][1], whi[mt][kt][2], whi[mt][kt][3], bh0, bh1);
                        mma_bf16(acc[mt][nt], whi[mt][kt][0], whi[mt][kt][1], whi[mt][kt][2], whi[mt][kt][3], bl0, bl1);
                        mma_bf16(acc[mt][nt], wlo[mt][kt][0], wlo[mt][kt][1], wlo[mt][kt][2], wlo[mt][kt][3], bh0, bh1);
                    }
                }
        }
        {
            char* xb = smem + SM_X + (t & 1) * XBUF;
#pragma unroll
            for (int nt = 0; nt < 4; nt++)
#pragma unroll
                for (int kt = 0; kt < 2; kt++) {
                    uint32_t off = (uint32_t)((g4 + 8 * nt) * XPITCH + (32 * w + 16 * kt + 2 * t4) * 2);
                    uint32_t bh0 = *(const uint32_t*)(xb + off);
                    uint32_t bh1 = *(const uint32_t*)(xb + off + 16);
                    uint32_t bl0 = *(const uint32_t*)(xb + XPLANE + off);
                    uint32_t bl1 = *(const uint32_t*)(xb + XPLANE + off + 16);
#pragma unroll
                    for (int mt = 0; mt < 2; mt++) {
                        mma_bf16(acc[mt][nt], xwhi[mt][kt][0], xwhi[mt][kt][1], xwhi[mt][kt][2], xwhi[mt][kt][3], bh0, bh1);
                        mma_bf16(acc[mt][nt], xwhi[mt][kt][0], xwhi[mt][kt][1], xwhi[mt][kt][2], xwhi[mt][kt][3], bl0, bl1);
                        mma_bf16(acc[mt][nt], xwlo[mt][kt][0], xwlo[mt][kt][1], xwlo[mt][kt][2], xwlo[mt][kt][3], bh0, bh1);
                    }
                }
        }

        // ---- store split-K partials: red[w][row][b], pitch 40 ----
        {
            float* rw = redp + w * 1280;
#pragma unroll
            for (int mt = 0; mt < 2; mt++)
#pragma unroll
                for (int nt = 0; nt < 4; nt++) {
                    int row0 = mt * 16 + g4;
                    int cc = 8 * nt + 2 * t4;
                    *(float2*)&rw[row0 * 40 + cc] = make_float2(acc[mt][nt][0], acc[mt][nt][1]);
                    *(float2*)&rw[(row0 + 8) * 40 + cc] = make_float2(acc[mt][nt][2], acc[mt][nt][3]);
                }
        }

        // ---- prefetch x[t+1] into other x buffer via cp.async ----
        if (t + 1 < TT) {
            char* xn = smem + SM_X + ((t + 1) & 1) * XBUF;
#pragma unroll
            for (int j = 0; j < 8; j++) {
                int q = tid + NTH * j;
                int row = q >> 6;
                int c8 = q & 63;
                size_t src = ((size_t)row * TT + (t + 1)) * II + c8 * 4;
                cp_async8(smem_u32(xn + row * XPITCH + c8 * 8), g_xbhi + src);
                cp_async8(smem_u32(xn + XPLANE + row * XPITCH + c8 * 8), g_xblo + src);
            }
            asm volatile("cp.async.commit_group;" ::: "memory");
        }
        __syncthreads();

        // ---- activation: reduce 8 partials + bias, update c/h, publish ----
        {
            float gv[4];
#pragma unroll
            for (int g = 0; g < 4; g++) {
                float s = bias_r[g];
                const int row = g * 8 + colL;
#pragma unroll
                for (int w2 = 0; w2 < 8; w2++)
                    s += redp[w2 * 1280 + row * 40 + b_act];
                gv[g] = s;
            }
            float ig = sigf(gv[0]);
            float fg = sigf(gv[1]);
            float gt = tanhf(gv[2]);
            float og = sigf(gv[3]);
            float cn = fmaf(fg, c_reg, ig * gt);
            float hn = og * tanhf(cn);
            c_reg = cn;

            // issue output store early (independent of the sync chain)
            out[((size_t)b_act * TT + t) * HH + colG] = hn;
            if (t == TT - 1 && tails) {
                out[BTH + (long long)b_act * HH + colG] = hn;
                out[BTH + (long long)BB * HH + (long long)b_act * HH + colG] = cn;
            }

            __nv_bfloat16 hh = __float2bfloat16(hn);
            const int hidx = b_act * HH + colG;
            g_hhi[(t + 1) & 1][hidx] = hh;
            g_hlo[(t + 1) & 1][hidx] = __float2bfloat16(hn - __bfloat162float(hh));
            __threadfence();
            asm volatile("cp.async.wait_all;" ::: "memory");
            __syncthreads();
            if (tid == 0) *(volatile int*)&g_flag[cta * 32] = F + t + 2;
        }
    }
}

// ---------------------------------------------------------------------------
// Inputs (metadata order): x, h0, c0, W_ih, W_hh, b_ih, b_hh
// Output: concat(result[B,T,H], h_f[1,B,H], c_f[1,B,H])
// ---------------------------------------------------------------------------
extern "C" void kernel_launch(void* const* d_in, const int* in_sizes, int n_in,
                              void* d_out, int out_size) {
    const float* x   = (const float*)d_in[0];
    const float* h0  = (const float*)d_in[1];
    const float* c0  = (const float*)d_in[2];
    const float* Wih = (const float*)d_in[3];
    const float* Whh = (const float*)d_in[4];
    const float* bih = (const float*)d_in[5];
    const float* bhh = (const float*)d_in[6];
    float* out = (float*)d_out;

    cudaFuncSetAttribute(lstm_fused, cudaFuncAttributeMaxDynamicSharedMemorySize, SM_TOT);

    xconv_kernel<<<2048, 256>>>(x);
    lstm_fused<<<NCTA_R, NTH, SM_TOT>>>(h0, c0, Wih, Whh, bih, bhh, out, (long long)out_size);
}

// round 7
// speedup vs baseline: 1.7794x; 1.1148x over previous
#include <cuda_runtime.h>
#include <cuda_bf16.h>
#include <cstdint>

#define BB 32
#define TT 2048
#define II 256
#define HH 512
#define GG 2048   // 4*H

#define NCTA_R 64
#define NTH  256

// Scratch (device globals — no runtime allocation allowed; zero-initialized)
__device__ __nv_bfloat16 g_xbhi[BB * TT * II];    // x hi plane [b][t][i] (32 MB)
__device__ __nv_bfloat16 g_xblo[BB * TT * II];    // x lo plane (32 MB)
__device__ uint32_t g_hp[2][BB * HH];             // ping-pong hidden, packed hi|lo bf16
__device__ int g_flag[NCTA_R * 32];               // per-CTA monotonic flags (128B apart)

// ---------------------------------------------------------------------------
// helpers
// ---------------------------------------------------------------------------
__device__ __forceinline__ void split2(float x, float y, uint32_t& hi, uint32_t& lo) {
    __nv_bfloat162 h = __floats2bfloat162_rn(x, y);
    float rx = x - __bfloat162float(h.x);
    float ry = y - __bfloat162float(h.y);
    __nv_bfloat162 l = __floats2bfloat162_rn(rx, ry);
    hi = *(uint32_t*)&h;
    lo = *(uint32_t*)&l;
}

__device__ __forceinline__ uint32_t packhl(float v) {
    __nv_bfloat16 h = __float2bfloat16(v);
    float r = v - __bfloat162float(h);
    __nv_bfloat16 lo = __float2bfloat16(r);
    unsigned short uh = *reinterpret_cast<unsigned short*>(&h);
    unsigned short ul = *reinterpret_cast<unsigned short*>(&lo);
    return (uint32_t)uh | ((uint32_t)ul << 16);
}

__device__ __forceinline__ void mma_bf16(float* c,
                                         uint32_t a0, uint32_t a1, uint32_t a2, uint32_t a3,
                                         uint32_t b0, uint32_t b1) {
    asm volatile(
        "mma.sync.aligned.m16n8k16.row.col.f32.bf16.bf16.f32 "
        "{%0,%1,%2,%3}, {%4,%5,%6,%7}, {%8,%9}, {%0,%1,%2,%3};"
        : "+f"(c[0]), "+f"(c[1]), "+f"(c[2]), "+f"(c[3])
        : "r"(a0), "r"(a1), "r"(a2), "r"(a3), "r"(b0), "r"(b1));
}

__device__ __forceinline__ float sigf(float v) {
    return __fdividef(1.0f, 1.0f + __expf(-v));
}
__device__ __forceinline__ float tanhfast(float v) {
    return __fdividef(2.0f, 1.0f + __expf(-2.0f * v)) - 1.0f;
}

__device__ __forceinline__ uint32_t smem_u32(const void* p) {
    uint32_t a;
    asm("{ .reg .u64 t; cvta.to.shared.u64 t, %1; cvt.u32.u64 %0, t; }" : "=r"(a) : "l"(p));
    return a;
}

__device__ __forceinline__ void cp_async8(uint32_t dst, const void* src) {
    asm volatile("cp.async.ca.shared.global [%0], [%1], 8;" :: "r"(dst), "l"(src) : "memory");
}

// Load one kt's worth of h B-fragments straight from global (packed hi|lo).
// f[nt][0..3] = bh0, bh1, bl0, bl1
__device__ __forceinline__ void load_hfrag(uint32_t f[4][4], const uint32_t* __restrict__ hp,
                                           int g4, int koff) {
#pragma unroll
    for (int nt = 0; nt < 4; nt++) {
        const uint32_t* rp = hp + (g4 + 8 * nt) * HH + koff;
        uint2 ca = __ldcg((const uint2*)rp);
        uint2 cb = __ldcg((const uint2*)(rp + 8));
        f[nt][0] = __byte_perm(ca.x, ca.y, 0x5410);
        f[nt][2] = __byte_perm(ca.x, ca.y, 0x7632);
        f[nt][1] = __byte_perm(cb.x, cb.y, 0x5410);
        f[nt][3] = __byte_perm(cb.x, cb.y, 0x7632);
    }
}

// ---------------------------------------------------------------------------
// Kernel 0: convert x to bf16 hi/lo planes (layout preserved [b][t][i])
// ---------------------------------------------------------------------------
__global__ void __launch_bounds__(256) xconv_kernel(const float* __restrict__ x) {
    const float2* src = (const float2*)x;
    uint32_t* dhi = (uint32_t*)g_xbhi;
    uint32_t* dlo = (uint32_t*)g_xblo;
    size_t n2 = (size_t)BB * TT * II / 2;
    for (size_t i = blockIdx.x * 256 + threadIdx.x; i < n2; i += (size_t)gridDim.x * 256) {
        float2 v = src[i];
        uint32_t hi, lo;
        split2(v.x, v.y, hi, lo);
        dhi[i] = hi;
        dlo[i] = lo;
    }
}

// smem layout (bytes)
#define SM_X   0                     // 2 bufs x (hi 16896 + lo 16896) = 67584
#define XPITCH 528
#define XPLANE 16896                 // 32 * 528
#define XBUF   33792                 // hi+lo
#define SM_RED 67584                 // 8*32*36*4 = 36864  (f32 [8][32][36])
#define SM_TOT 104448

// ---------------------------------------------------------------------------
// Fused persistent LSTM. 64 CTAs x 256 threads (8 warps).
// CTA owns 8 H-cols -> 32 gate rows (r = gate*8 + colL).
// gates = W_hh*h (K=512, 8-way K-split) + W_ih*x[t] (K=256) + bias,
// m16n8k16 bf16 3-pass; W frags in registers; h B-frags loaded DIRECTLY
// from packed global (no smem staging), software-pipelined over kt with
// the x MMAs as latency cover.
// ---------------------------------------------------------------------------
__global__ void __launch_bounds__(NTH, 1) lstm_fused(
    const float* __restrict__ h0,
    const float* __restrict__ c0,
    const float* __restrict__ Wih,
    const float* __restrict__ Whh,
    const float* __restrict__ bih,
    const float* __restrict__ bhh,
    float* __restrict__ out,
    long long out_size)
{
    extern __shared__ char smem[];
    float* redp = (float*)(smem + SM_RED);

    const int tid = threadIdx.x;
    const int cta = blockIdx.x;
    const int col0 = cta * 8;

    const int w  = tid >> 5;   // warp: h K-slice [64w, 64w+64), x K-slice [32w, 32w+32)
    const int l  = tid & 31;
    const int g4 = l >> 2;
    const int t4 = l & 3;

    // --- W_hh fragments (hi/lo) in registers ---
    uint32_t whi[2][4][4], wlo[2][4][4];
#pragma unroll
    for (int mt = 0; mt < 2; mt++)
#pragma unroll
        for (int kt = 0; kt < 4; kt++) {
            const int k = 64 * w + 16 * kt + 2 * t4;
            const int r0 = mt * 16 + g4;
            const int r1 = r0 + 8;
            const int grow0 = (r0 >> 3) * HH + col0 + (r0 & 7);
            const int grow1 = (r1 >> 3) * HH + col0 + (r1 & 7);
            float2 v;
            v = *(const float2*)(Whh + (size_t)grow0 * HH + k);
            split2(v.x, v.y, whi[mt][kt][0], wlo[mt][kt][0]);
            v = *(const float2*)(Whh + (size_t)grow1 * HH + k);
            split2(v.x, v.y, whi[mt][kt][1], wlo[mt][kt][1]);
            v = *(const float2*)(Whh + (size_t)grow0 * HH + k + 8);
            split2(v.x, v.y, whi[mt][kt][2], wlo[mt][kt][2]);
            v = *(const float2*)(Whh + (size_t)grow1 * HH + k + 8);
            split2(v.x, v.y, whi[mt][kt][3], wlo[mt][kt][3]);
        }

    // --- W_ih fragments (hi/lo) in registers ---
    uint32_t xwhi[2][2][4], xwlo[2][2][4];
#pragma unroll
    for (int mt = 0; mt < 2; mt++)
#pragma unroll
        for (int kt = 0; kt < 2; kt++) {
            const int k = 32 * w + 16 * kt + 2 * t4;
            const int r0 = mt * 16 + g4;
            const int r1 = r0 + 8;
            const int grow0 = (r0 >> 3) * HH + col0 + (r0 & 7);
            const int grow1 = (r1 >> 3) * HH + col0 + (r1 & 7);
            float2 v;
            v = *(const float2*)(Wih + (size_t)grow0 * II + k);
            split2(v.x, v.y, xwhi[mt][kt][0], xwlo[mt][kt][0]);
            v = *(const float2*)(Wih + (size_t)grow1 * II + k);
            split2(v.x, v.y, xwhi[mt][kt][1], xwlo[mt][kt][1]);
            v = *(const float2*)(Wih + (size_t)grow0 * II + k + 8);
            split2(v.x, v.y, xwhi[mt][kt][2], xwlo[mt][kt][2]);
            v = *(const float2*)(Wih + (size_t)grow1 * II + k + 8);
            split2(v.x, v.y, xwhi[mt][kt][3], xwlo[mt][kt][3]);
        }

    // --- activation identity + per-thread state ---
    const int colL = tid & 7;
    const int b_act = tid >> 3;
    const int colG = col0 + colL;
    float c_reg = c0[b_act * HH + colG];
    float bias_r[4];
#pragma unroll
    for (int g = 0; g < 4; g++)
        bias_r[g] = bih[g * HH + colG] + bhh[g * HH + colG];

    // --- flag base (monotonic across graph replays) ---
    const int F = *(volatile int*)&g_flag[cta * 32];

    // --- stage h0 slice (producer identity) into buffer 0 (packed) ---
    g_hp[0][b_act * HH + colG] = packhl(h0[b_act * HH + colG]);

    // --- stage x[0] into x buffer 0 via cp.async ---
    {
        char* xb = smem + SM_X;
#pragma unroll
        for (int j = 0; j < 8; j++) {
            int q = tid + NTH * j;
            int row = q >> 6;
            int c8 = q & 63;
            size_t src = ((size_t)row * TT + 0) * II + c8 * 4;
            cp_async8(smem_u32(xb + row * XPITCH + c8 * 8), g_xbhi + src);
            cp_async8(smem_u32(xb + XPLANE + row * XPITCH + c8 * 8), g_xblo + src);
        }
        asm volatile("cp.async.commit_group;" ::: "memory");
        asm volatile("cp.async.wait_all;" ::: "memory");
    }
    __threadfence();
    __syncthreads();
    if (tid == 0) *(volatile int*)&g_flag[cta * 32] = F + 1;

    const long long BTH = (long long)BB * TT * HH;
    const bool tails = (out_size >= BTH + 2LL * BB * HH);

    const int pidx = (8 * w + (l & 7)) * 32;   // producer flag index
    const bool poller = (l < 8);               // only 8 lanes generate poll traffic

    for (int t = 0; t < TT; t++) {
        // ---- issue x[t+1] prefetch FIRST (whole step to land) ----
        if (t + 1 < TT) {
            char* xn = smem + SM_X + ((t + 1) & 1) * XBUF;
#pragma unroll
            for (int j = 0; j < 8; j++) {
                int q = tid + NTH * j;
                int row = q >> 6;
                int c8 = q & 63;
                size_t src = ((size_t)row * TT + (t + 1)) * II + c8 * 4;
                cp_async8(smem_u32(xn + row * XPITCH + c8 * 8), g_xbhi + src);
                cp_async8(smem_u32(xn + XPLANE + row * XPITCH + c8 * 8), g_xblo + src);
            }
            asm volatile("cp.async.commit_group;" ::: "memory");
        }

        // ---- poll producer flags (lanes<8 only) ----
        {
            const int need = F + t + 1;
            while (__any_sync(0xffffffffu,
                              poller && (*(volatile int*)&g_flag[pidx] < need)))
                __nanosleep(20);
        }
        __threadfence();   // acquire

        const uint32_t* hp = g_hp[t & 1];
        const int kbase = 64 * w + 2 * t4;

        // ---- kick off h frag loads for kt0, kt1 (fly during x MMAs) ----
        uint32_t fA[4][4], fB[4][4];
        load_hfrag(fA, hp, g4, kbase + 0);
        load_hfrag(fB, hp, g4, kbase + 16);

        // ---- x MMAs (48) from smem (latency cover for h LDGs) ----
        float acc[2][4][4] = {};
        {
            char* xb = smem + SM_X + (t & 1) * XBUF;
#pragma unroll
            for (int nt = 0; nt < 4; nt++)
#pragma unroll
                for (int kt = 0; kt < 2; kt++) {
                    uint32_t off = (uint32_t)((g4 + 8 * nt) * XPITCH + (32 * w + 16 * kt + 2 * t4) * 2);
                    uint32_t bh0 = *(const uint32_t*)(xb + off);
                    uint32_t bh1 = *(const uint32_t*)(xb + off + 16);
                    uint32_t bl0 = *(const uint32_t*)(xb + XPLANE + off);
                    uint32_t bl1 = *(const uint32_t*)(xb + XPLANE + off + 16);
#pragma unroll
                    for (int mt = 0; mt < 2; mt++) {
                        mma_bf16(acc[mt][nt], xwhi[mt][kt][0], xwhi[mt][kt][1], xwhi[mt][kt][2], xwhi[mt][kt][3], bh0, bh1);
                        mma_bf16(acc[mt][nt], xwhi[mt][kt][0], xwhi[mt][kt][1], xwhi[mt][kt][2], xwhi[mt][kt][3], bl0, bl1);
                        mma_bf16(acc[mt][nt], xwlo[mt][kt][0], xwlo[mt][kt][1], xwlo[mt][kt][2], xwlo[mt][kt][3], bh0, bh1);
                    }
                }
        }

        // ---- h MMAs, pipelined: consume kt, prefetch kt+2 ----
#define HMMA_KT(F_, KT_) \
        { _Pragma("unroll") \
          for (int nt = 0; nt < 4; nt++) { \
            _Pragma("unroll") \
            for (int mt = 0; mt < 2; mt++) { \
                mma_bf16(acc[mt][nt], whi[mt][KT_][0], whi[mt][KT_][1], whi[mt][KT_][2], whi[mt][KT_][3], F_[nt][0], F_[nt][1]); \
                mma_bf16(acc[mt][nt], whi[mt][KT_][0], whi[mt][KT_][1], whi[mt][KT_][2], whi[mt][KT_][3], F_[nt][2], F_[nt][3]); \
                mma_bf16(acc[mt][nt], wlo[mt][KT_][0], wlo[mt][KT_][1], wlo[mt][KT_][2], wlo[mt][KT_][3], F_[nt][0], F_[nt][1]); \
            } } }

        HMMA_KT(fA, 0);
        load_hfrag(fA, hp, g4, kbase + 32);
        HMMA_KT(fB, 1);
        load_hfrag(fB, hp, g4, kbase + 48);
        HMMA_KT(fA, 2);
        HMMA_KT(fB, 3);
#undef HMMA_KT

        // ---- store split-K partials: red[w][row][b], pitch 36 ----
        {
            float* rw = redp + w * 1152;
#pragma unroll
            for (int mt = 0; mt < 2; mt++)
#pragma unroll
                for (int nt = 0; nt < 4; nt++) {
                    int row0 = mt * 16 + g4;
                    int cc = 8 * nt + 2 * t4;
                    *(float2*)&rw[row0 * 36 + cc] = make_float2(acc[mt][nt][0], acc[mt][nt][1]);
                    *(float2*)&rw[(row0 + 8) * 36 + cc] = make_float2(acc[mt][nt][2], acc[mt][nt][3]);
                }
        }
        __syncthreads();

        // ---- reduce + activations + publish ----
        {
            float gv[4];
#pragma unroll
            for (int g = 0; g < 4; g++) {
                float s = bias_r[g];
                const int row = g * 8 + colL;
#pragma unroll
                for (int w2 = 0; w2 < 8; w2++)
                    s += redp[w2 * 1152 + row * 36 + b_act];
                gv[g] = s;
            }
            float ig = sigf(gv[0]);
            float fg = sigf(gv[1]);
            float gt = tanhfast(gv[2]);
            float og = sigf(gv[3]);
            float cn = fmaf(fg, c_reg, ig * gt);
            float hn = og * tanhfast(cn);
            c_reg = cn;

            // publish h (single packed STG.32), fence, barrier, flag
            g_hp[(t + 1) & 1][b_act * HH + colG] = packhl(hn);
            __threadfence();
            asm volatile("cp.async.wait_all;" ::: "memory");
            __syncthreads();
            if (tid == 0) *(volatile int*)&g_flag[cta * 32] = F + t + 2;

            // output stores AFTER the publish chain (off critical path)
            out[((size_t)b_act * TT + t) * HH + colG] = hn;
            if (t == TT - 1 && tails) {
                out[BTH + (long long)b_act * HH + colG] = hn;
                out[BTH + (long long)BB * HH + (long long)b_act * HH + colG] = cn;
            }
        }
    }
}

// ---------------------------------------------------------------------------
// Inputs (metadata order): x, h0, c0, W_ih, W_hh, b_ih, b_hh
// Output: concat(result[B,T,H], h_f[1,B,H], c_f[1,B,H])
// ---------------------------------------------------------------------------
extern "C" void kernel_launch(void* const* d_in, const int* in_sizes, int n_in,
                              void* d_out, int out_size) {
    const float* x   = (const float*)d_in[0];
    const float* h0  = (const float*)d_in[1];
    const float* c0  = (const float*)d_in[2];
    const float* Wih = (const float*)d_in[3];
    const float* Whh = (const float*)d_in[4];
    const float* bih = (const float*)d_in[5];
    const float* bhh = (const float*)d_in[6];
    float* out = (float*)d_out;

    cudaFuncSetAttribute(lstm_fused, cudaFuncAttributeMaxDynamicSharedMemorySize, SM_TOT);

    xconv_kernel<<<2048, 256>>>(x);
    lstm_fused<<<NCTA_R, NTH, SM_TOT>>>(h0, c0, Wih, Whh, bih, bhh, out, (long long)out_size);
}